// round 6
// baseline (speedup 1.0000x reference)
#include <cuda_runtime.h>
#include <math.h>

#define BS 8
#define QN 1000
#define NC 92
#define TN 300
#define QP1 1001
#define TP1 301
#define SCSZ (BS*QP1*TP1)          // 2,410,408
#define MTROW (QN+TN)              // 1300
#define CPL 10                     // columns per DP lane (30 lanes * 10 = 300)
#define NR 4                       // cost ring depth
#define NW 4                       // output ring depth
#define CHUNK 250                  // traceback rows staged per smem load
#define FULLM 0xffffffffu

__device__ float g_prob[BS*QN*NC];
__device__ float g_cost[BS*QN*TN];
__device__ unsigned g_packed[BS*QP1*32];     // 20-bit ptr codes per lane-word
__device__ int g_lbl64;                      // 1 if labels are int64, 0 if int32

// ---------------- label dtype detection ----------------
__global__ void detect_kernel(const unsigned* __restrict__ lbl_raw) {
    int allzero = 1;
    #pragma unroll
    for (int k = 1; k < 16; k += 2) allzero &= (lbl_raw[k] == 0u);
    g_lbl64 = allzero;
}

// ---------------- softmax over logits [BS*QN, NC] -> g_prob ----------------
__global__ void softmax_kernel(const float* __restrict__ logits) {
    int warpId = (blockIdx.x * blockDim.x + threadIdx.x) >> 5;
    int lane = threadIdx.x & 31;
    if (warpId >= BS * QN) return;
    const float* row = logits + warpId * NC;
    float v0 = (lane < NC)      ? row[lane]      : -INFINITY;
    float v1 = (lane + 32 < NC) ? row[lane + 32] : -INFINITY;
    float v2 = (lane + 64 < NC) ? row[lane + 64] : -INFINITY;
    float m = fmaxf(v0, fmaxf(v1, v2));
    #pragma unroll
    for (int o = 16; o; o >>= 1) m = fmaxf(m, __shfl_xor_sync(FULLM, m, o));
    float e0 = (lane < NC)      ? expf(v0 - m) : 0.f;
    float e1 = (lane + 32 < NC) ? expf(v1 - m) : 0.f;
    float e2 = (lane + 64 < NC) ? expf(v2 - m) : 0.f;
    float s = e0 + e1 + e2;
    #pragma unroll
    for (int o = 16; o; o >>= 1) s += __shfl_xor_sync(FULLM, s, o);
    float* out = g_prob + warpId * NC;
    if (lane < NC)      out[lane]      = e0 / s;
    if (lane + 32 < NC) out[lane + 32] = e1 / s;
    if (lane + 64 < NC) out[lane + 64] = e2 / s;
}

// ---------------- cost matrix [BS, QN, TN] -> g_cost ----------------
__global__ void cost_kernel(const float* __restrict__ pred_boxes,
                            const int* __restrict__ tgt_labels,
                            const float* __restrict__ tgt_boxes) {
    int idx = blockIdx.x * blockDim.x + threadIdx.x;
    if (idx >= BS * QN * TN) return;
    int t = idx % TN;
    int bq = idx / TN;
    int b = bq / QN;

    float4 pb = ((const float4*)pred_boxes)[bq];
    float4 tb = ((const float4*)tgt_boxes)[b * TN + t];
    int li = b * TN + t;
    int lbl = g_lbl64 ? tgt_labels[li * 2] : tgt_labels[li];
    lbl = max(0, min(NC - 1, lbl));
    float p = g_prob[bq * NC + lbl];

    float l1 = fabsf(pb.x - tb.x) + fabsf(pb.y - tb.y) +
               fabsf(pb.z - tb.z) + fabsf(pb.w - tb.w);

    float px1 = pb.x - 0.5f * pb.z, py1 = pb.y - 0.5f * pb.w;
    float px2 = pb.x + 0.5f * pb.z, py2 = pb.y + 0.5f * pb.w;
    float tx1 = tb.x - 0.5f * tb.z, ty1 = tb.y - 0.5f * tb.w;
    float tx2 = tb.x + 0.5f * tb.z, ty2 = tb.y + 0.5f * tb.w;

    float a1 = (px2 - px1) * (py2 - py1);
    float a2 = (tx2 - tx1) * (ty2 - ty1);
    float ltx = fmaxf(px1, tx1), lty = fmaxf(py1, ty1);
    float rbx = fminf(px2, tx2), rby = fminf(py2, ty2);
    float iw = fmaxf(rbx - ltx, 0.f), ih = fmaxf(rby - lty, 0.f);
    float inter = iw * ih;
    float uni = a1 + a2 - inter;
    float iou = inter / uni;
    float cx1 = fminf(px1, tx1), cy1 = fminf(py1, ty1);
    float cx2 = fmaxf(px2, tx2), cy2 = fmaxf(py2, ty2);
    float cw = fmaxf(cx2 - cx1, 0.f), ch = fmaxf(cy2 - cy1, 0.f);
    float ac = cw * ch;
    float giou = iou - (ac - uni) / ac;

    g_cost[idx] = 5.0f * l1 - p - 2.0f * giou;
}

// ---------------- DP: warp-specialized, one block per batch ----------------
// warp0=DP (registers), warp1=score writer, warp2=ptr writer, warp3=cost loader
__global__ void __launch_bounds__(128, 1) dp_kernel(float* __restrict__ out) {
    __shared__ float costRing[NR][304];
    __shared__ float scoreRing[NW][304];
    __shared__ unsigned codeRing[NW][32];
    __shared__ unsigned chunkBuf[CHUNK * 32];   // 32 KB
    __shared__ volatile int f_cost, f_dp, f_ws, f_wp;

    int b = blockIdx.x;
    int tid = threadIdx.x;
    int lane = tid & 31;
    int w = tid >> 5;

    float* scores = out + (size_t)b * QP1 * TP1;
    float* ptrs   = out + SCSZ + (size_t)b * QP1 * TP1;
    unsigned* pkB = g_packed + (size_t)b * QP1 * 32;

    // boundary init: row 0, col 0
    for (int k = tid; k < TP1; k += 128) {
        scores[k] = 0.f;
        ptrs[k] = (k == 0) ? 0.f : 1.f;
    }
    for (int k = tid + 1; k <= QN; k += 128) {
        scores[(size_t)k * TP1] = 0.f;
        ptrs[(size_t)k * TP1] = -1.f;
    }
    if (tid == 0) { f_cost = 0; f_dp = 0; f_ws = 0; f_wp = 0; }
    __syncthreads();

    if (w == 3) {
        // -------- cost-row loader --------
        const float* cb = g_cost + (size_t)b * QN * TN;
        for (int i = 1; i <= QN; i++) {
            while (f_dp < i - NR) __nanosleep(40);
            int sl = i & (NR - 1);
            const float* src = cb + (size_t)(i - 1) * TN;
            #pragma unroll
            for (int m = 0; m < 10; m++) {
                int c = lane + 32 * m;
                if (c < TN) costRing[sl][c] = src[c];
            }
            __syncwarp();
            __threadfence_block();
            if (lane == 0) f_cost = i;
        }
    } else if (w == 0) {
        // -------- DP warp --------
        bool act = lane < 30;
        int base = lane * CPL;                  // 0-based cost-col index
        float prev[CPL];
        #pragma unroll
        for (int k = 0; k < CPL; k++) prev[k] = 0.f;
        float leftPrev = 0.f;

        for (int i = 1; i <= QN; i++) {
            while (f_cost < i) __nanosleep(20);
            int cs = i & (NR - 1);
            float cr[CPL];
            if (act) {
                #pragma unroll
                for (int k = 0; k < CPL; k++) cr[k] = costRing[cs][base + k];
            }
            float dg[CPL], pf[CPL];
            float run = -INFINITY;
            if (act) {
                float pl = leftPrev;
                #pragma unroll
                for (int k = 0; k < CPL; k++) {
                    float r = 10000.0f - cr[k];
                    float d = pl + r;
                    dg[k] = d;
                    pl = prev[k];
                    run = fmaxf(run, fmaxf(d, prev[k]));
                    pf[k] = run;
                }
            }
            // radix-4 inclusive warp max-scan over lane totals
            float T = run;
            float t1 = __shfl_up_sync(FULLM, T, 1);
            float t2 = __shfl_up_sync(FULLM, T, 2);
            float t3 = __shfl_up_sync(FULLM, T, 3);
            if (lane >= 1) T = fmaxf(T, t1);
            if (lane >= 2) T = fmaxf(T, t2);
            if (lane >= 3) T = fmaxf(T, t3);
            t1 = __shfl_up_sync(FULLM, T, 4);
            t2 = __shfl_up_sync(FULLM, T, 8);
            t3 = __shfl_up_sync(FULLM, T, 12);
            if (lane >= 4)  T = fmaxf(T, t1);
            if (lane >= 8)  T = fmaxf(T, t2);
            if (lane >= 12) T = fmaxf(T, t3);
            t1 = __shfl_up_sync(FULLM, T, 16);
            if (lane >= 16) T = fmaxf(T, t1);
            float off = __shfl_up_sync(FULLM, T, 1);
            if (lane == 0) off = -INFINITY;

            // output ring backpressure
            while (f_ws < i - NW || f_wp < i - NW) __nanosleep(40);
            int os = i & (NW - 1);
            unsigned word = 0;
            if (act) {
                #pragma unroll
                for (int k = 0; k < CPL; k++) {
                    float s = fmaxf(pf[k], off);
                    unsigned e = (dg[k] == s) ? 0u : ((prev[k] == s) ? 1u : 2u);
                    word |= e << (2 * k);
                    prev[k] = s;
                    scoreRing[os][base + k] = s;
                }
                codeRing[os][lane] = word;
                pkB[(size_t)i * 32 + lane] = word;
            }
            leftPrev = __shfl_up_sync(FULLM, prev[CPL - 1], 1);
            if (lane == 0) leftPrev = 0.f;
            __syncwarp();
            __threadfence_block();
            if (lane == 0) f_dp = i;
        }
    } else if (w == 1) {
        // -------- score writer --------
        for (int i = 1; i <= QN; i++) {
            while (f_dp < i) __nanosleep(40);
            int sl = i & (NW - 1);
            float* dst = scores + (size_t)i * TP1 + 1;
            #pragma unroll
            for (int m = 0; m < 10; m++) {
                int c = lane + 32 * m;
                if (c < TN) dst[c] = scoreRing[sl][c];
            }
            __syncwarp();
            __threadfence_block();
            if (lane == 0) f_ws = i;
        }
    } else {
        // -------- pointer writer --------
        for (int i = 1; i <= QN; i++) {
            while (f_dp < i) __nanosleep(40);
            int sl = i & (NW - 1);
            float* dst = ptrs + (size_t)i * TP1 + 1;
            #pragma unroll
            for (int m = 0; m < 10; m++) {
                int c = lane + 32 * m;
                if (c < TN) {
                    unsigned wd = codeRing[sl][c / CPL];
                    unsigned e = (wd >> (2 * (c % CPL))) & 3u;
                    dst[c] = (e == 0u) ? 0.f : ((e == 1u) ? -1.f : 1.f);
                }
            }
            __syncwarp();
            __threadfence_block();
            if (lane == 0) f_wp = i;
        }
    }
    __syncthreads();

    // ---- traceback, chunked through smem ----
    float* mt = out + 2 * (size_t)SCSZ + (size_t)b * MTROW * 2;
    int r = QN, c = TN, st = 0;

    #pragma unroll 1
    for (int k = 0; k < QN / CHUNK; k++) {
        int hi = QN - k * CHUNK;
        int lo = hi - (CHUNK - 1);
        const unsigned* src = pkB + (size_t)lo * 32;
        for (int x = tid; x < CHUNK * 32; x += 128) chunkBuf[x] = src[x];
        __syncthreads();
        if (tid == 0) {
            while (st < MTROW && r >= lo) {
                int p;
                if (c == 0) {
                    p = -1;
                } else {
                    int ci = c - 1;
                    unsigned wd = chunkBuf[(r - lo) * 32 + ci / CPL];
                    int e = (wd >> (2 * (ci % CPL))) & 3;
                    p = (e == 0) ? 0 : ((e == 1) ? -1 : 1);
                }
                int nr = (p == 1) ? r : r - 1;
                int nc = (p == -1) ? c : c - 1;
                bool ismatch = (p == 0);
                int oidx = (MTROW - 1 - st) * 2;
                mt[oidx]     = ismatch ? (float)nr : -1.f;
                mt[oidx + 1] = ismatch ? (float)nc : -1.f;
                r = nr; c = nc; st++;
            }
        }
        __syncthreads();
    }
    if (tid == 0) {
        while (st < MTROW) {
            int oidx = (MTROW - 1 - st) * 2;
            mt[oidx] = -1.f;
            mt[oidx + 1] = -1.f;
            st++;
        }
    }
}

extern "C" void kernel_launch(void* const* d_in, const int* in_sizes, int n_in,
                              void* d_out, int out_size) {
    const float* pred_logits = (const float*)d_in[0];
    const float* pred_boxes  = (const float*)d_in[1];
    const int*   tgt_labels  = (const int*)d_in[2];
    const float* tgt_boxes   = (const float*)d_in[3];
    float* out = (float*)d_out;

    detect_kernel<<<1, 1>>>((const unsigned*)d_in[2]);
    softmax_kernel<<<(BS * QN + 7) / 8, 256>>>(pred_logits);
    cost_kernel<<<(BS * QN * TN + 255) / 256, 256>>>(pred_boxes, tgt_labels, tgt_boxes);
    dp_kernel<<<BS, 128>>>(out);
}

// round 7
// speedup vs baseline: 1.3587x; 1.3587x over previous
#include <cuda_runtime.h>
#include <math.h>

#define BS 8
#define QN 1000
#define NC 92
#define TN 300
#define QP1 1001
#define TP1 301
#define SCSZ (BS*QP1*TP1)          // 2,410,408
#define MTROW (QN+TN)              // 1300
#define CPL 10                     // columns per DP lane (30 lanes * 10 = 300)
#define CHUNK 250                  // traceback rows staged per smem load
#define FULLM 0xffffffffu
#define NEGINF (-INFINITY)

__device__ float g_prob[BS*QN*NC];
__device__ float g_rw[BS*QN*TN];             // reward = 10000 - cost
__device__ unsigned g_packed[BS*QP1*32];     // 2-bit ptr codes, 1 word per lane
__device__ int g_lbl64;                      // 1 if labels are int64, 0 if int32

// ---------------- label dtype detection ----------------
__global__ void detect_kernel(const unsigned* __restrict__ lbl_raw) {
    int allzero = 1;
    #pragma unroll
    for (int k = 1; k < 16; k += 2) allzero &= (lbl_raw[k] == 0u);
    g_lbl64 = allzero;
}

// ---------------- softmax over logits [BS*QN, NC] -> g_prob ----------------
__global__ void softmax_kernel(const float* __restrict__ logits) {
    int warpId = (blockIdx.x * blockDim.x + threadIdx.x) >> 5;
    int lane = threadIdx.x & 31;
    if (warpId >= BS * QN) return;
    const float* row = logits + warpId * NC;
    float v0 = (lane < NC)      ? row[lane]      : NEGINF;
    float v1 = (lane + 32 < NC) ? row[lane + 32] : NEGINF;
    float v2 = (lane + 64 < NC) ? row[lane + 64] : NEGINF;
    float m = fmaxf(v0, fmaxf(v1, v2));
    #pragma unroll
    for (int o = 16; o; o >>= 1) m = fmaxf(m, __shfl_xor_sync(FULLM, m, o));
    float e0 = (lane < NC)      ? expf(v0 - m) : 0.f;
    float e1 = (lane + 32 < NC) ? expf(v1 - m) : 0.f;
    float e2 = (lane + 64 < NC) ? expf(v2 - m) : 0.f;
    float s = e0 + e1 + e2;
    #pragma unroll
    for (int o = 16; o; o >>= 1) s += __shfl_xor_sync(FULLM, s, o);
    float* out = g_prob + warpId * NC;
    if (lane < NC)      out[lane]      = e0 / s;
    if (lane + 32 < NC) out[lane + 32] = e1 / s;
    if (lane + 64 < NC) out[lane + 64] = e2 / s;
}

// ---------------- cost matrix -> rewards [BS, QN, TN] ----------------
__global__ void cost_kernel(const float* __restrict__ pred_boxes,
                            const int* __restrict__ tgt_labels,
                            const float* __restrict__ tgt_boxes) {
    int idx = blockIdx.x * blockDim.x + threadIdx.x;
    if (idx >= BS * QN * TN) return;
    int t = idx % TN;
    int bq = idx / TN;
    int b = bq / QN;

    float4 pb = ((const float4*)pred_boxes)[bq];
    float4 tb = ((const float4*)tgt_boxes)[b * TN + t];
    int li = b * TN + t;
    int lbl = g_lbl64 ? tgt_labels[li * 2] : tgt_labels[li];
    lbl = max(0, min(NC - 1, lbl));
    float p = g_prob[bq * NC + lbl];

    float l1 = fabsf(pb.x - tb.x) + fabsf(pb.y - tb.y) +
               fabsf(pb.z - tb.z) + fabsf(pb.w - tb.w);

    float px1 = pb.x - 0.5f * pb.z, py1 = pb.y - 0.5f * pb.w;
    float px2 = pb.x + 0.5f * pb.z, py2 = pb.y + 0.5f * pb.w;
    float tx1 = tb.x - 0.5f * tb.z, ty1 = tb.y - 0.5f * tb.w;
    float tx2 = tb.x + 0.5f * tb.z, ty2 = tb.y + 0.5f * tb.w;

    float a1 = (px2 - px1) * (py2 - py1);
    float a2 = (tx2 - tx1) * (ty2 - ty1);
    float ltx = fmaxf(px1, tx1), lty = fmaxf(py1, ty1);
    float rbx = fminf(px2, tx2), rby = fminf(py2, ty2);
    float iw = fmaxf(rbx - ltx, 0.f), ih = fmaxf(rby - lty, 0.f);
    float inter = iw * ih;
    float uni = a1 + a2 - inter;
    float iou = inter / uni;
    float cx1 = fminf(px1, tx1), cy1 = fminf(py1, ty1);
    float cx2 = fmaxf(px2, tx2), cy2 = fmaxf(py2, ty2);
    float cw = fmaxf(cx2 - cx1, 0.f), ch = fmaxf(cy2 - cy1, 0.f);
    float ac = cw * ch;
    float giou = iou - (ac - uni) / ac;

    float cost = 5.0f * l1 - p - 2.0f * giou;
    g_rw[idx] = 10000.0f - cost;             // reward (bit-identical to DP-side sub)
}

// ---------------- DP + traceback: one WARP per batch ----------------
// out layout (float32): [scores 8x1001x301][pointers 8x1001x301][matches 8x1300x2]
__global__ void __launch_bounds__(32, 1) dp_kernel(float* __restrict__ out) {
    __shared__ unsigned chunkBuf[CHUNK * 32];   // 32 KB

    int b = blockIdx.x;
    int lane = threadIdx.x;
    bool act = lane < 30;
    int base = lane * CPL;

    float* scores = out + (size_t)b * QP1 * TP1;
    unsigned* pkB = g_packed + (size_t)b * QP1 * 32;
    const float* rw = g_rw + (size_t)b * QN * TN;

    float prev[CPL];
    #pragma unroll
    for (int k = 0; k < CPL; k++) prev[k] = 0.f;
    float leftPrev = 0.f;

    // depth-2 prefetch buffers (5 x float2 = 10 rewards per lane)
    float2 bufA[5], bufB[5];
    if (act) {
        const float2* p0 = (const float2*)(rw + base);
        const float2* p1 = (const float2*)(rw + TN + base);
        #pragma unroll
        for (int q = 0; q < 5; q++) { bufA[q] = p0[q]; bufB[q] = p1[q]; }
    }

    #define DP_BODY(I, BUF)                                                     \
    {                                                                           \
        float rk[CPL];                                                          \
        _Pragma("unroll")                                                       \
        for (int q = 0; q < 5; q++) { rk[2*q] = BUF[q].x; rk[2*q+1] = BUF[q].y; } \
        /* prefetch row (I+1) into BUF (consumed at iteration I+2) */           \
        if (act && (I) + 1 < QN) {                                              \
            const float2* pp = (const float2*)(rw + (size_t)((I) + 1) * TN + base); \
            _Pragma("unroll")                                                   \
            for (int q = 0; q < 5; q++) BUF[q] = pp[q];                         \
        }                                                                       \
        float dg[CPL], m[CPL];                                                  \
        dg[0] = leftPrev + rk[0];                                               \
        _Pragma("unroll")                                                       \
        for (int k = 1; k < CPL; k++) dg[k] = prev[k-1] + rk[k];                \
        _Pragma("unroll")                                                       \
        for (int k = 0; k < CPL; k++) m[k] = fmaxf(dg[k], prev[k]);             \
        /* 4-level in-lane inclusive prefix max (depth 16 cyc) */               \
        float p1_[CPL], p2_[CPL], p4_[CPL], pf[CPL];                            \
        p1_[0] = m[0];                                                          \
        _Pragma("unroll")                                                       \
        for (int k = 1; k < CPL; k++) p1_[k] = fmaxf(m[k], m[k-1]);             \
        p2_[0] = p1_[0]; p2_[1] = p1_[1];                                       \
        _Pragma("unroll")                                                       \
        for (int k = 2; k < CPL; k++) p2_[k] = fmaxf(p1_[k], p1_[k-2]);         \
        _Pragma("unroll")                                                       \
        for (int k = 0; k < 4; k++) p4_[k] = p2_[k];                            \
        _Pragma("unroll")                                                       \
        for (int k = 4; k < CPL; k++) p4_[k] = fmaxf(p2_[k], p2_[k-4]);         \
        _Pragma("unroll")                                                       \
        for (int k = 0; k < 8; k++) pf[k] = p4_[k];                             \
        _Pragma("unroll")                                                       \
        for (int k = 8; k < CPL; k++) pf[k] = fmaxf(p4_[k], p4_[k-8]);          \
        float T = act ? pf[CPL-1] : NEGINF;                                     \
        /* exclusive radix-4 warp max-scan */                                   \
        float E = __shfl_up_sync(FULLM, T, 1);                                  \
        E = (lane >= 1) ? E : NEGINF;                                           \
        {                                                                       \
            float a1 = __shfl_up_sync(FULLM, E, 1);                             \
            float a2 = __shfl_up_sync(FULLM, E, 2);                             \
            float a3 = __shfl_up_sync(FULLM, E, 3);                             \
            a1 = (lane >= 1) ? a1 : NEGINF;                                     \
            a2 = (lane >= 2) ? a2 : NEGINF;                                     \
            a3 = (lane >= 3) ? a3 : NEGINF;                                     \
            E = fmaxf(fmaxf(a1, a2), fmaxf(a3, E));                             \
            a1 = __shfl_up_sync(FULLM, E, 4);                                   \
            a2 = __shfl_up_sync(FULLM, E, 8);                                   \
            a3 = __shfl_up_sync(FULLM, E, 12);                                  \
            a1 = (lane >= 4)  ? a1 : NEGINF;                                    \
            a2 = (lane >= 8)  ? a2 : NEGINF;                                    \
            a3 = (lane >= 12) ? a3 : NEGINF;                                    \
            E = fmaxf(fmaxf(a1, a2), fmaxf(a3, E));                             \
            a1 = __shfl_up_sync(FULLM, E, 16);                                  \
            if (lane >= 16) E = fmaxf(E, a1);                                   \
        }                                                                       \
        float sn[CPL];                                                          \
        _Pragma("unroll")                                                       \
        for (int k = 0; k < CPL; k++) sn[k] = fmaxf(pf[k], E);                  \
        if (act) {                                                              \
            unsigned word = 0;                                                  \
            float* dst = scores + (size_t)(I) * TP1 + 1 + base;                 \
            _Pragma("unroll")                                                   \
            for (int k = 0; k < CPL; k++) {                                     \
                unsigned e = (dg[k] == sn[k]) ? 0u : ((prev[k] == sn[k]) ? 1u : 2u); \
                word |= e << (2 * k);                                           \
                dst[k] = sn[k];                                                 \
            }                                                                   \
            pkB[(size_t)(I) * 32 + lane] = word;                                \
        }                                                                       \
        float l9 = __shfl_up_sync(FULLM, sn[CPL-1], 1);                         \
        leftPrev = (lane >= 1) ? l9 : 0.f;                                      \
        _Pragma("unroll")                                                       \
        for (int k = 0; k < CPL; k++) prev[k] = sn[k];                          \
    }

    #pragma unroll 1
    for (int i = 1; i <= QN; i += 2) {
        DP_BODY(i, bufA)
        DP_BODY(i + 1, bufB)
    }
    #undef DP_BODY

    __threadfence_block();
    __syncwarp();

    // ---- traceback, chunked through smem ----
    float* mt = out + 2 * (size_t)SCSZ + (size_t)b * MTROW * 2;
    int r = QN, c = TN, st = 0;

    #pragma unroll 1
    for (int k = 0; k < QN / CHUNK; k++) {
        int hi = QN - k * CHUNK;
        int lo = hi - (CHUNK - 1);
        const unsigned* src = pkB + (size_t)lo * 32;
        #pragma unroll 4
        for (int x = lane; x < CHUNK * 32; x += 32) chunkBuf[x] = src[x];
        __syncwarp();
        if (lane == 0) {
            while (st < MTROW && r >= lo) {
                int p;
                if (c == 0) {
                    p = -1;
                } else {
                    int ci = c - 1;
                    unsigned wd = chunkBuf[(r - lo) * 32 + ci / CPL];
                    int e = (wd >> (2 * (ci % CPL))) & 3;
                    p = (e == 0) ? 0 : ((e == 1) ? -1 : 1);
                }
                int nr = (p == 1) ? r : r - 1;
                int nc = (p == -1) ? c : c - 1;
                bool ismatch = (p == 0);
                int oidx = (MTROW - 1 - st) * 2;
                mt[oidx]     = ismatch ? (float)nr : -1.f;
                mt[oidx + 1] = ismatch ? (float)nc : -1.f;
                r = nr; c = nc; st++;
            }
        }
        __syncwarp();
    }
    if (lane == 0) {
        while (st < MTROW) {
            int oidx = (MTROW - 1 - st) * 2;
            mt[oidx] = -1.f;
            mt[oidx + 1] = -1.f;
            st++;
        }
    }
}

// ---------------- pointers + score boundaries from packed codes ----------------
__global__ void recon_kernel(float* __restrict__ out) {
    int idx = blockIdx.x * blockDim.x + threadIdx.x;
    if (idx >= BS * QP1 * TP1) return;
    int j = idx % TP1;
    int bi = idx / TP1;
    int i = bi % QP1;
    int b = bi / QP1;

    float pv;
    if (i == 0) {
        pv = (j == 0) ? 0.f : 1.f;
    } else if (j == 0) {
        pv = -1.f;
    } else {
        int ci = j - 1;
        unsigned wd = g_packed[((size_t)b * QP1 + i) * 32 + ci / CPL];
        unsigned e = (wd >> (2 * (ci % CPL))) & 3u;
        pv = (e == 0u) ? 0.f : ((e == 1u) ? -1.f : 1.f);
    }
    out[SCSZ + (size_t)idx] = pv;
    if (i == 0 || j == 0) out[idx] = 0.f;     // score boundaries
}

extern "C" void kernel_launch(void* const* d_in, const int* in_sizes, int n_in,
                              void* d_out, int out_size) {
    const float* pred_logits = (const float*)d_in[0];
    const float* pred_boxes  = (const float*)d_in[1];
    const int*   tgt_labels  = (const int*)d_in[2];
    const float* tgt_boxes   = (const float*)d_in[3];
    float* out = (float*)d_out;

    detect_kernel<<<1, 1>>>((const unsigned*)d_in[2]);
    softmax_kernel<<<(BS * QN + 7) / 8, 256>>>(pred_logits);
    cost_kernel<<<(BS * QN * TN + 255) / 256, 256>>>(pred_boxes, tgt_labels, tgt_boxes);
    dp_kernel<<<BS, 32>>>(out);
    recon_kernel<<<(BS * QP1 * TP1 + 255) / 256, 256>>>(out);
}